// round 2
// baseline (speedup 1.0000x reference)
#include <cuda_runtime.h>

// Problem constants
#define B_   4
#define H_   16
#define T_   2048
#define C_   1024
#define D_   64
#define BH_  (B_*H_)

typedef unsigned long long u64;

// ---------- packed f32x2 helpers (Blackwell sm_100+) ----------
__device__ __forceinline__ void fma2(u64 &acc, u64 a, u64 b){
    asm("fma.rn.f32x2 %0, %1, %2, %0;" : "+l"(acc) : "l"(a), "l"(b));
}
__device__ __forceinline__ u64 pk2(float lo, float hi){
    u64 r;
    asm("mov.b64 %0, {%1, %2};" : "=l"(r)
        : "r"(__float_as_uint(lo)), "r"(__float_as_uint(hi)));
    return r;
}
__device__ __forceinline__ float2 upk2(u64 p){
    unsigned lo, hi;
    asm("mov.b64 {%0, %1}, %2;" : "=r"(lo), "=r"(hi) : "l"(p));
    return make_float2(__uint_as_float(lo), __uint_as_float(hi));
}
__device__ __forceinline__ float hadd2(u64 p){
    float2 v = upk2(p); return v.x + v.y;
}
__device__ __forceinline__ u64 ld2s(const float* p){   // 8B-aligned smem read
    return *reinterpret_cast<const u64*>(p);
}

// ---------- device scratch (allocation-free rule: __device__ globals) ----------
__device__ float g_q  [BH_*T_*D_];   // [bh][t][d]
__device__ float g_k  [BH_*T_*D_];
__device__ float g_v  [BH_*T_*D_];
__device__ float g_att[BH_*T_*D_];   // attention output pre-projection
__device__ float g_invZ[BH_*T_];     // per-key 1/Z

// =====================================================================
// K1: QKV projection.  For (b,h,z): out[t,d] = sum_c x[b,t,c] * W_z[h,c,d]
// Tile 128(t) x 64(d), K-tile 16. 256 threads, each 8x4 outputs (f32x2 packed over d).
// =====================================================================
__global__ __launch_bounds__(256) void qkv_kernel(
    const float* __restrict__ x,
    const float* __restrict__ Wq,
    const float* __restrict__ Wk,
    const float* __restrict__ Wv)
{
    __shared__ float As[16][128];   // [k][m]
    __shared__ float Bs[16][64];    // [k][n]

    int tid = threadIdx.x;
    int bh  = blockIdx.y;
    int b   = bh >> 4, h = bh & 15;
    int t0  = blockIdx.x * 128;

    const float* W = (blockIdx.z == 0 ? Wq : (blockIdx.z == 1 ? Wk : Wv)) + (size_t)h * C_ * D_;
    float* out = (blockIdx.z == 0 ? g_q : (blockIdx.z == 1 ? g_k : g_v)) + ((size_t)bh * T_ + t0) * D_;
    const float* A = x + ((size_t)b * T_ + t0) * C_;

    int tr = tid >> 4;      // 0..15 -> rows tr*8..tr*8+7
    int tc = tid & 15;      // 0..15 -> cols tc*4..tc*4+3

    u64 acc[8][2];
    #pragma unroll
    for (int j = 0; j < 8; j++){ acc[j][0] = 0ull; acc[j][1] = 0ull; }

    for (int k0 = 0; k0 < C_; k0 += 16){
        // A tile, transposed store
        #pragma unroll
        for (int i = 0; i < 2; i++){
            int idx = tid + i * 256;
            int m = idx >> 2, kq = (idx & 3) * 4;
            float4 v4 = *reinterpret_cast<const float4*>(A + (size_t)m * C_ + k0 + kq);
            As[kq+0][m] = v4.x; As[kq+1][m] = v4.y; As[kq+2][m] = v4.z; As[kq+3][m] = v4.w;
        }
        // B tile
        {
            int r = tid >> 4, cq = (tid & 15) * 4;
            *reinterpret_cast<float4*>(&Bs[r][cq]) =
                *reinterpret_cast<const float4*>(W + (size_t)(k0 + r) * D_ + cq);
        }
        __syncthreads();
        #pragma unroll
        for (int kk = 0; kk < 16; kk++){
            float4 a0 = *reinterpret_cast<const float4*>(&As[kk][tr*8]);
            float4 a1 = *reinterpret_cast<const float4*>(&As[kk][tr*8+4]);
            float4 bq = *reinterpret_cast<const float4*>(&Bs[kk][tc*4]);
            u64 b01 = pk2(bq.x, bq.y), b23 = pk2(bq.z, bq.w);
            float av[8] = {a0.x,a0.y,a0.z,a0.w,a1.x,a1.y,a1.z,a1.w};
            #pragma unroll
            for (int j = 0; j < 8; j++){
                u64 aj = pk2(av[j], av[j]);
                fma2(acc[j][0], aj, b01);
                fma2(acc[j][1], aj, b23);
            }
        }
        __syncthreads();
    }
    #pragma unroll
    for (int j = 0; j < 8; j++){
        float2 lo = upk2(acc[j][0]);
        float2 hi = upk2(acc[j][1]);
        float4 o = make_float4(lo.x, lo.y, hi.x, hi.y);
        *reinterpret_cast<float4*>(out + (size_t)(tr*8 + j) * D_ + tc*4) = o;
    }
}

// =====================================================================
// K2: per-key column sums.  invZ[bh][s] = 1 / sum_{t>=s} exp(0.125 * q_t.k_s)
// Block: 64 keys, streams 64-query tiles from t=s0..T. f32x2 packed over d-pairs.
// =====================================================================
__global__ __launch_bounds__(256) void colsum_kernel()
{
    __shared__ float Ks[64][66];   // [s][d] (+pad)
    __shared__ float Qs[64][66];   // [t][d] (+pad)

    int tid = threadIdx.x;
    int bh  = blockIdx.y;
    int s0  = blockIdx.x * 64;
    const float* kb = g_k + (size_t)bh * T_ * D_;
    const float* qb = g_q + (size_t)bh * T_ * D_;

    // load K tile once
    #pragma unroll
    for (int i = 0; i < 8; i++){
        int idx = tid + i * 256;                // 2048 float2
        int r = idx >> 5, c2 = idx & 31;
        *reinterpret_cast<float2*>(&Ks[r][c2*2]) =
            *reinterpret_cast<const float2*>(kb + (size_t)(s0 + r) * D_ + c2*2);
    }

    int tr = tid >> 4, tc = tid & 15;           // 4t x 4s per thread
    float colsum[4] = {0.f, 0.f, 0.f, 0.f};

    for (int t0 = s0; t0 < T_; t0 += 64){
        __syncthreads();                        // Qs free (also covers Ks-load on iter 0 via next sync)
        #pragma unroll
        for (int i = 0; i < 8; i++){
            int idx = tid + i * 256;
            int r = idx >> 5, c2 = idx & 31;
            *reinterpret_cast<float2*>(&Qs[r][c2*2]) =
                *reinterpret_cast<const float2*>(qb + (size_t)(t0 + r) * D_ + c2*2);
        }
        __syncthreads();

        u64 acc[4][4];
        #pragma unroll
        for (int j = 0; j < 4; j++)
            #pragma unroll
            for (int i = 0; i < 4; i++) acc[j][i] = 0ull;

        #pragma unroll
        for (int dd = 0; dd < 32; dd++){
            u64 a2[4], b2[4];
            #pragma unroll
            for (int j = 0; j < 4; j++) a2[j] = ld2s(&Qs[tr*4 + j][dd*2]);
            #pragma unroll
            for (int i = 0; i < 4; i++) b2[i] = ld2s(&Ks[tc*4 + i][dd*2]);
            #pragma unroll
            for (int j = 0; j < 4; j++)
                #pragma unroll
                for (int i = 0; i < 4; i++) fma2(acc[j][i], a2[j], b2[i]);
        }

        bool diag = (t0 == s0);
        #pragma unroll
        for (int j = 0; j < 4; j++){
            int tg = t0 + tr*4 + j;
            #pragma unroll
            for (int i = 0; i < 4; i++){
                float S = hadd2(acc[j][i]);
                int sg = s0 + tc*4 + i;
                float w = (!diag || tg >= sg) ? __expf(S * 0.125f) : 0.0f;
                colsum[i] += w;
            }
        }
    }

    __syncthreads();
    float* red = &Ks[0][0];                     // reuse
    #pragma unroll
    for (int i = 0; i < 4; i++) red[tr*64 + tc*4 + i] = colsum[i];
    __syncthreads();
    if (tid < 64){
        float z = 0.f;
        #pragma unroll
        for (int r = 0; r < 16; r++) z += red[r*64 + tid];
        g_invZ[(size_t)bh * T_ + s0 + tid] = 1.0f / z;
    }
}

// =====================================================================
// K3: attention output.  out[t,:] = sum_{s<=t} exp(0.125*q_t.k_s) * invZ[s] * v[s,:]
// Block: 64 queries; streams 32-key tiles s0=0..t0+32.
// gemm1: S = Q.K^T (packed over d), exp -> Ws smem; gemm2: out += W.V (packed over s).
// =====================================================================
__global__ __launch_bounds__(256) void attn_kernel()
{
    __shared__ float Qs[64][66];   // [t][d]
    __shared__ float Ks[32][66];   // [s][d]
    __shared__ float Vs[64][34];   // [d][s]
    __shared__ float Ws[64][34];   // [t][s]

    int tid = threadIdx.x;
    int bh  = blockIdx.y;
    int t0  = (int)(gridDim.x - 1 - blockIdx.x) * 64;   // big tiles first
    const float* qb = g_q + (size_t)bh * T_ * D_;
    const float* kb = g_k + (size_t)bh * T_ * D_;
    const float* vb = g_v + (size_t)bh * T_ * D_;
    const float* iz = g_invZ + (size_t)bh * T_;

    // load Q tile
    #pragma unroll
    for (int i = 0; i < 8; i++){
        int idx = tid + i * 256;
        int r = idx >> 5, c2 = idx & 31;
        *reinterpret_cast<float2*>(&Qs[r][c2*2]) =
            *reinterpret_cast<const float2*>(qb + (size_t)(t0 + r) * D_ + c2*2);
    }

    int tr = tid >> 4;    // gemm1: t rows tr*4+j ; gemm2 same rows
    int tc = tid & 15;    // gemm1: s cols tc*2+i ; gemm2: d cols tc*4+i

    u64 oacc[4][4];       // out acc [t][d], packed over s-parity
    #pragma unroll
    for (int j = 0; j < 4; j++)
        #pragma unroll
        for (int i = 0; i < 4; i++) oacc[j][i] = 0ull;

    for (int s0 = 0; s0 <= t0 + 32; s0 += 32){
        __syncthreads();   // prev-iter Ks/Vs/Ws readers done (also covers Qs load on iter 0)

        // K tile [32][64] -> Ks[s][d]
        #pragma unroll
        for (int i = 0; i < 4; i++){
            int idx = tid + i * 256;
            int r = idx >> 5, c2 = idx & 31;
            *reinterpret_cast<float2*>(&Ks[r][c2*2]) =
                *reinterpret_cast<const float2*>(kb + (size_t)(s0 + r) * D_ + c2*2);
        }
        // V tile transposed -> Vs[d][s]
        #pragma unroll
        for (int i = 0; i < 2; i++){
            int idx = tid + i * 256;            // 512 float4 = 32 rows x 16
            int r = idx >> 4, cq = (idx & 15) * 4;
            float4 v4 = *reinterpret_cast<const float4*>(vb + (size_t)(s0 + r) * D_ + cq);
            Vs[cq+0][r] = v4.x; Vs[cq+1][r] = v4.y; Vs[cq+2][r] = v4.z; Vs[cq+3][r] = v4.w;
        }
        __syncthreads();

        // gemm1: S[4t][2s]
        u64 acc[4][2];
        #pragma unroll
        for (int j = 0; j < 4; j++){ acc[j][0] = 0ull; acc[j][1] = 0ull; }
        #pragma unroll
        for (int dd = 0; dd < 32; dd++){
            u64 a2[4], b2[2];
            #pragma unroll
            for (int j = 0; j < 4; j++) a2[j] = ld2s(&Qs[tr*4 + j][dd*2]);
            #pragma unroll
            for (int i = 0; i < 2; i++) b2[i] = ld2s(&Ks[tc*2 + i][dd*2]);
            #pragma unroll
            for (int j = 0; j < 4; j++)
                #pragma unroll
                for (int i = 0; i < 2; i++) fma2(acc[j][i], a2[j], b2[i]);
        }

        bool msk = (s0 >= t0);
        float izv0 = iz[s0 + tc*2];
        float izv1 = iz[s0 + tc*2 + 1];
        #pragma unroll
        for (int j = 0; j < 4; j++){
            int tg = t0 + tr*4 + j;
            float S0 = hadd2(acc[j][0]);
            float S1 = hadd2(acc[j][1]);
            int sg0 = s0 + tc*2, sg1 = sg0 + 1;
            float w0 = (!msk || tg >= sg0) ? __expf(S0 * 0.125f) * izv0 : 0.0f;
            float w1 = (!msk || tg >= sg1) ? __expf(S1 * 0.125f) * izv1 : 0.0f;
            *reinterpret_cast<float2*>(&Ws[tr*4 + j][tc*2]) = make_float2(w0, w1);
        }
        __syncthreads();

        // gemm2: out[4t][4d] += W @ V   (packed over s-pairs)
        #pragma unroll
        for (int sp = 0; sp < 16; sp++){
            u64 a2[4], b2[4];
            #pragma unroll
            for (int j = 0; j < 4; j++) a2[j] = ld2s(&Ws[tr*4 + j][sp*2]);
            #pragma unroll
            for (int i = 0; i < 4; i++) b2[i] = ld2s(&Vs[tc*4 + i][sp*2]);
            #pragma unroll
            for (int j = 0; j < 4; j++)
                #pragma unroll
                for (int i = 0; i < 4; i++) fma2(oacc[j][i], a2[j], b2[i]);
        }
    }

    float* ob = g_att + ((size_t)bh * T_ + t0) * D_;
    #pragma unroll
    for (int j = 0; j < 4; j++){
        float4 o = make_float4(hadd2(oacc[j][0]), hadd2(oacc[j][1]),
                               hadd2(oacc[j][2]), hadd2(oacc[j][3]));
        *reinterpret_cast<float4*>(ob + (size_t)(tr*4 + j) * D_ + tc*4) = o;
    }
}

// =====================================================================
// K4: output projection.  out[m, n] = sum_c att2[m][c] * Wo[c][n] + bo[n]
// att2[m][c]: m=b*T+t, c=h*64+d  ->  g_att[((b*16+h)*T + t)*64 + d]
// =====================================================================
__global__ __launch_bounds__(256) void oproj_kernel(
    const float* __restrict__ Wo,
    const float* __restrict__ bo,
    float* __restrict__ out)
{
    __shared__ float As[16][128];
    __shared__ float Bs[16][64];

    int tid = threadIdx.x;
    int m0  = blockIdx.x * 128;
    int n0  = blockIdx.y * 64;
    int tr = tid >> 4, tc = tid & 15;

    u64 acc[8][2];
    #pragma unroll
    for (int j = 0; j < 8; j++){ acc[j][0] = 0ull; acc[j][1] = 0ull; }

    for (int k0 = 0; k0 < C_; k0 += 16){
        int hk = k0 >> 6, dk = k0 & 63;        // K-tile stays within one head (16|64)
        #pragma unroll
        for (int i = 0; i < 2; i++){
            int idx = tid + i * 256;
            int m = idx >> 2, kq = (idx & 3) * 4;
            int mg = m0 + m;
            int b = mg >> 11, t = mg & 2047;
            const float* src = g_att + (((size_t)(b * H_ + hk)) * T_ + t) * D_ + dk + kq;
            float4 v4 = *reinterpret_cast<const float4*>(src);
            As[kq+0][m] = v4.x; As[kq+1][m] = v4.y; As[kq+2][m] = v4.z; As[kq+3][m] = v4.w;
        }
        {
            int r = tid >> 4, cq = (tid & 15) * 4;
            *reinterpret_cast<float4*>(&Bs[r][cq]) =
                *reinterpret_cast<const float4*>(Wo + (size_t)(k0 + r) * C_ + n0 + cq);
        }
        __syncthreads();
        #pragma unroll
        for (int kk = 0; kk < 16; kk++){
            float4 a0 = *reinterpret_cast<const float4*>(&As[kk][tr*8]);
            float4 a1 = *reinterpret_cast<const float4*>(&As[kk][tr*8+4]);
            float4 bq = *reinterpret_cast<const float4*>(&Bs[kk][tc*4]);
            u64 b01 = pk2(bq.x, bq.y), b23 = pk2(bq.z, bq.w);
            float av[8] = {a0.x,a0.y,a0.z,a0.w,a1.x,a1.y,a1.z,a1.w};
            #pragma unroll
            for (int j = 0; j < 8; j++){
                u64 aj = pk2(av[j], av[j]);
                fma2(acc[j][0], aj, b01);
                fma2(acc[j][1], aj, b23);
            }
        }
        __syncthreads();
    }

    float4 bias = *reinterpret_cast<const float4*>(bo + n0 + tc*4);
    #pragma unroll
    for (int j = 0; j < 8; j++){
        float2 lo = upk2(acc[j][0]);
        float2 hi = upk2(acc[j][1]);
        float4 o = make_float4(lo.x + bias.x, lo.y + bias.y, hi.x + bias.z, hi.y + bias.w);
        *reinterpret_cast<float4*>(out + (size_t)(m0 + tr*8 + j) * C_ + n0 + tc*4) = o;
    }
}

// =====================================================================
extern "C" void kernel_launch(void* const* d_in, const int* in_sizes, int n_in,
                              void* d_out, int out_size)
{
    const float* x  = (const float*)d_in[0];
    const float* Wq = (const float*)d_in[1];
    const float* Wk = (const float*)d_in[2];
    const float* Wv = (const float*)d_in[3];
    const float* Wo = (const float*)d_in[4];
    const float* bo = (const float*)d_in[5];
    float* out = (float*)d_out;

    qkv_kernel   <<<dim3(T_/128, BH_, 3), 256>>>(x, Wq, Wk, Wv);
    colsum_kernel<<<dim3(T_/64,  BH_),    256>>>();
    attn_kernel  <<<dim3(T_/64,  BH_),    256>>>();
    oproj_kernel <<<dim3((B_*T_)/128, C_/64), 256>>>(Wo, bo, out);
}

// round 3
// speedup vs baseline: 1.0001x; 1.0001x over previous
#include <cuda_runtime.h>

// Problem constants
#define B_   4
#define H_   16
#define T_   2048
#define C_   1024
#define D_   64
#define BH_  (B_*H_)

typedef unsigned long long u64;

// ---------- packed f32x2 helpers (Blackwell sm_100+) ----------
__device__ __forceinline__ void fma2(u64 &acc, u64 a, u64 b){
    asm("fma.rn.f32x2 %0, %1, %2, %0;" : "+l"(acc) : "l"(a), "l"(b));
}
__device__ __forceinline__ u64 pk2(float lo, float hi){
    u64 r;
    asm("mov.b64 %0, {%1, %2};" : "=l"(r)
        : "r"(__float_as_uint(lo)), "r"(__float_as_uint(hi)));
    return r;
}
__device__ __forceinline__ float2 upk2(u64 p){
    unsigned lo, hi;
    asm("mov.b64 {%0, %1}, %2;" : "=r"(lo), "=r"(hi) : "l"(p));
    return make_float2(__uint_as_float(lo), __uint_as_float(hi));
}
__device__ __forceinline__ float hadd2(u64 p){
    float2 v = upk2(p); return v.x + v.y;
}
__device__ __forceinline__ u64 ld2s(const float* p){   // 8B-aligned smem read
    return *reinterpret_cast<const u64*>(p);
}

// ---------- device scratch (allocation-free rule: __device__ globals) ----------
__device__ float g_q  [BH_*T_*D_];   // [bh][t][d]
__device__ float g_k  [BH_*T_*D_];
__device__ float g_v  [BH_*T_*D_];
__device__ float g_att[BH_*T_*D_];   // attention output pre-projection
__device__ float g_invZ[BH_*T_];     // per-key 1/Z

// =====================================================================
// K1: QKV projection.  For (b,h,z): out[t,d] = sum_c x[b,t,c] * W_z[h,c,d]
// Tile 128(t) x 64(d), K-tile 16. 256 threads, each 8x4 outputs (f32x2 packed over d).
// =====================================================================
__global__ __launch_bounds__(256) void qkv_kernel(
    const float* __restrict__ x,
    const float* __restrict__ Wq,
    const float* __restrict__ Wk,
    const float* __restrict__ Wv)
{
    __shared__ float As[16][128];   // [k][m]
    __shared__ float Bs[16][64];    // [k][n]

    int tid = threadIdx.x;
    int bh  = blockIdx.y;
    int b   = bh >> 4, h = bh & 15;
    int t0  = blockIdx.x * 128;

    const float* W = (blockIdx.z == 0 ? Wq : (blockIdx.z == 1 ? Wk : Wv)) + (size_t)h * C_ * D_;
    float* out = (blockIdx.z == 0 ? g_q : (blockIdx.z == 1 ? g_k : g_v)) + ((size_t)bh * T_ + t0) * D_;
    const float* A = x + ((size_t)b * T_ + t0) * C_;

    int tr = tid >> 4;      // 0..15 -> rows tr*8..tr*8+7
    int tc = tid & 15;      // 0..15 -> cols tc*4..tc*4+3

    u64 acc[8][2];
    #pragma unroll
    for (int j = 0; j < 8; j++){ acc[j][0] = 0ull; acc[j][1] = 0ull; }

    for (int k0 = 0; k0 < C_; k0 += 16){
        // A tile, transposed store
        #pragma unroll
        for (int i = 0; i < 2; i++){
            int idx = tid + i * 256;
            int m = idx >> 2, kq = (idx & 3) * 4;
            float4 v4 = *reinterpret_cast<const float4*>(A + (size_t)m * C_ + k0 + kq);
            As[kq+0][m] = v4.x; As[kq+1][m] = v4.y; As[kq+2][m] = v4.z; As[kq+3][m] = v4.w;
        }
        // B tile
        {
            int r = tid >> 4, cq = (tid & 15) * 4;
            *reinterpret_cast<float4*>(&Bs[r][cq]) =
                *reinterpret_cast<const float4*>(W + (size_t)(k0 + r) * D_ + cq);
        }
        __syncthreads();
        #pragma unroll
        for (int kk = 0; kk < 16; kk++){
            float4 a0 = *reinterpret_cast<const float4*>(&As[kk][tr*8]);
            float4 a1 = *reinterpret_cast<const float4*>(&As[kk][tr*8+4]);
            float4 bq = *reinterpret_cast<const float4*>(&Bs[kk][tc*4]);
            u64 b01 = pk2(bq.x, bq.y), b23 = pk2(bq.z, bq.w);
            float av[8] = {a0.x,a0.y,a0.z,a0.w,a1.x,a1.y,a1.z,a1.w};
            #pragma unroll
            for (int j = 0; j < 8; j++){
                u64 aj = pk2(av[j], av[j]);
                fma2(acc[j][0], aj, b01);
                fma2(acc[j][1], aj, b23);
            }
        }
        __syncthreads();
    }
    #pragma unroll
    for (int j = 0; j < 8; j++){
        float2 lo = upk2(acc[j][0]);
        float2 hi = upk2(acc[j][1]);
        float4 o = make_float4(lo.x, lo.y, hi.x, hi.y);
        *reinterpret_cast<float4*>(out + (size_t)(tr*8 + j) * D_ + tc*4) = o;
    }
}

// =====================================================================
// K2: per-key column sums.  invZ[bh][s] = 1 / sum_{t>=s} exp(0.125 * q_t.k_s)
// Block: 64 keys, streams 64-query tiles from t=s0..T. f32x2 packed over d-pairs.
// =====================================================================
__global__ __launch_bounds__(256) void colsum_kernel()
{
    __shared__ float Ks[64][66];   // [s][d] (+pad)
    __shared__ float Qs[64][66];   // [t][d] (+pad)

    int tid = threadIdx.x;
    int bh  = blockIdx.y;
    int s0  = blockIdx.x * 64;
    const float* kb = g_k + (size_t)bh * T_ * D_;
    const float* qb = g_q + (size_t)bh * T_ * D_;

    // load K tile once
    #pragma unroll
    for (int i = 0; i < 8; i++){
        int idx = tid + i * 256;                // 2048 float2
        int r = idx >> 5, c2 = idx & 31;
        *reinterpret_cast<float2*>(&Ks[r][c2*2]) =
            *reinterpret_cast<const float2*>(kb + (size_t)(s0 + r) * D_ + c2*2);
    }

    int tr = tid >> 4, tc = tid & 15;           // 4t x 4s per thread
    float colsum[4] = {0.f, 0.f, 0.f, 0.f};

    for (int t0 = s0; t0 < T_; t0 += 64){
        __syncthreads();                        // Qs free (also covers Ks-load on iter 0 via next sync)
        #pragma unroll
        for (int i = 0; i < 8; i++){
            int idx = tid + i * 256;
            int r = idx >> 5, c2 = idx & 31;
            *reinterpret_cast<float2*>(&Qs[r][c2*2]) =
                *reinterpret_cast<const float2*>(qb + (size_t)(t0 + r) * D_ + c2*2);
        }
        __syncthreads();

        u64 acc[4][4];
        #pragma unroll
        for (int j = 0; j < 4; j++)
            #pragma unroll
            for (int i = 0; i < 4; i++) acc[j][i] = 0ull;

        #pragma unroll
        for (int dd = 0; dd < 32; dd++){
            u64 a2[4], b2[4];
            #pragma unroll
            for (int j = 0; j < 4; j++) a2[j] = ld2s(&Qs[tr*4 + j][dd*2]);
            #pragma unroll
            for (int i = 0; i < 4; i++) b2[i] = ld2s(&Ks[tc*4 + i][dd*2]);
            #pragma unroll
            for (int j = 0; j < 4; j++)
                #pragma unroll
                for (int i = 0; i < 4; i++) fma2(acc[j][i], a2[j], b2[i]);
        }

        bool diag = (t0 == s0);
        #pragma unroll
        for (int j = 0; j < 4; j++){
            int tg = t0 + tr*4 + j;
            #pragma unroll
            for (int i = 0; i < 4; i++){
                float S = hadd2(acc[j][i]);
                int sg = s0 + tc*4 + i;
                float w = (!diag || tg >= sg) ? __expf(S * 0.125f) : 0.0f;
                colsum[i] += w;
            }
        }
    }

    __syncthreads();
    float* red = &Ks[0][0];                     // reuse
    #pragma unroll
    for (int i = 0; i < 4; i++) red[tr*64 + tc*4 + i] = colsum[i];
    __syncthreads();
    if (tid < 64){
        float z = 0.f;
        #pragma unroll
        for (int r = 0; r < 16; r++) z += red[r*64 + tid];
        g_invZ[(size_t)bh * T_ + s0 + tid] = 1.0f / z;
    }
}

// =====================================================================
// K3: attention output.  out[t,:] = sum_{s<=t} exp(0.125*q_t.k_s) * invZ[s] * v[s,:]
// Block: 64 queries; streams 32-key tiles s0=0..t0+32.
// gemm1: S = Q.K^T (packed over d), exp -> Ws smem; gemm2: out += W.V (packed over s).
// =====================================================================
__global__ __launch_bounds__(256) void attn_kernel()
{
    __shared__ float Qs[64][66];   // [t][d]
    __shared__ float Ks[32][66];   // [s][d]
    __shared__ float Vs[64][34];   // [d][s]
    __shared__ float Ws[64][34];   // [t][s]

    int tid = threadIdx.x;
    int bh  = blockIdx.y;
    int t0  = (int)(gridDim.x - 1 - blockIdx.x) * 64;   // big tiles first
    const float* qb = g_q + (size_t)bh * T_ * D_;
    const float* kb = g_k + (size_t)bh * T_ * D_;
    const float* vb = g_v + (size_t)bh * T_ * D_;
    const float* iz = g_invZ + (size_t)bh * T_;

    // load Q tile
    #pragma unroll
    for (int i = 0; i < 8; i++){
        int idx = tid + i * 256;
        int r = idx >> 5, c2 = idx & 31;
        *reinterpret_cast<float2*>(&Qs[r][c2*2]) =
            *reinterpret_cast<const float2*>(qb + (size_t)(t0 + r) * D_ + c2*2);
    }

    int tr = tid >> 4;    // gemm1: t rows tr*4+j ; gemm2 same rows
    int tc = tid & 15;    // gemm1: s cols tc*2+i ; gemm2: d cols tc*4+i

    u64 oacc[4][4];       // out acc [t][d], packed over s-parity
    #pragma unroll
    for (int j = 0; j < 4; j++)
        #pragma unroll
        for (int i = 0; i < 4; i++) oacc[j][i] = 0ull;

    for (int s0 = 0; s0 <= t0 + 32; s0 += 32){
        __syncthreads();   // prev-iter Ks/Vs/Ws readers done (also covers Qs load on iter 0)

        // K tile [32][64] -> Ks[s][d]
        #pragma unroll
        for (int i = 0; i < 4; i++){
            int idx = tid + i * 256;
            int r = idx >> 5, c2 = idx & 31;
            *reinterpret_cast<float2*>(&Ks[r][c2*2]) =
                *reinterpret_cast<const float2*>(kb + (size_t)(s0 + r) * D_ + c2*2);
        }
        // V tile transposed -> Vs[d][s]
        #pragma unroll
        for (int i = 0; i < 2; i++){
            int idx = tid + i * 256;            // 512 float4 = 32 rows x 16
            int r = idx >> 4, cq = (idx & 15) * 4;
            float4 v4 = *reinterpret_cast<const float4*>(vb + (size_t)(s0 + r) * D_ + cq);
            Vs[cq+0][r] = v4.x; Vs[cq+1][r] = v4.y; Vs[cq+2][r] = v4.z; Vs[cq+3][r] = v4.w;
        }
        __syncthreads();

        // gemm1: S[4t][2s]
        u64 acc[4][2];
        #pragma unroll
        for (int j = 0; j < 4; j++){ acc[j][0] = 0ull; acc[j][1] = 0ull; }
        #pragma unroll
        for (int dd = 0; dd < 32; dd++){
            u64 a2[4], b2[2];
            #pragma unroll
            for (int j = 0; j < 4; j++) a2[j] = ld2s(&Qs[tr*4 + j][dd*2]);
            #pragma unroll
            for (int i = 0; i < 2; i++) b2[i] = ld2s(&Ks[tc*2 + i][dd*2]);
            #pragma unroll
            for (int j = 0; j < 4; j++)
                #pragma unroll
                for (int i = 0; i < 2; i++) fma2(acc[j][i], a2[j], b2[i]);
        }

        bool msk = (s0 >= t0);
        float izv0 = iz[s0 + tc*2];
        float izv1 = iz[s0 + tc*2 + 1];
        #pragma unroll
        for (int j = 0; j < 4; j++){
            int tg = t0 + tr*4 + j;
            float S0 = hadd2(acc[j][0]);
            float S1 = hadd2(acc[j][1]);
            int sg0 = s0 + tc*2, sg1 = sg0 + 1;
            float w0 = (!msk || tg >= sg0) ? __expf(S0 * 0.125f) * izv0 : 0.0f;
            float w1 = (!msk || tg >= sg1) ? __expf(S1 * 0.125f) * izv1 : 0.0f;
            *reinterpret_cast<float2*>(&Ws[tr*4 + j][tc*2]) = make_float2(w0, w1);
        }
        __syncthreads();

        // gemm2: out[4t][4d] += W @ V   (packed over s-pairs)
        #pragma unroll
        for (int sp = 0; sp < 16; sp++){
            u64 a2[4], b2[4];
            #pragma unroll
            for (int j = 0; j < 4; j++) a2[j] = ld2s(&Ws[tr*4 + j][sp*2]);
            #pragma unroll
            for (int i = 0; i < 4; i++) b2[i] = ld2s(&Vs[tc*4 + i][sp*2]);
            #pragma unroll
            for (int j = 0; j < 4; j++)
                #pragma unroll
                for (int i = 0; i < 4; i++) fma2(oacc[j][i], a2[j], b2[i]);
        }
    }

    float* ob = g_att + ((size_t)bh * T_ + t0) * D_;
    #pragma unroll
    for (int j = 0; j < 4; j++){
        float4 o = make_float4(hadd2(oacc[j][0]), hadd2(oacc[j][1]),
                               hadd2(oacc[j][2]), hadd2(oacc[j][3]));
        *reinterpret_cast<float4*>(ob + (size_t)(tr*4 + j) * D_ + tc*4) = o;
    }
}

// =====================================================================
// K4: output projection.  out[m, n] = sum_c att2[m][c] * Wo[c][n] + bo[n]
// att2[m][c]: m=b*T+t, c=h*64+d  ->  g_att[((b*16+h)*T + t)*64 + d]
// =====================================================================
__global__ __launch_bounds__(256) void oproj_kernel(
    const float* __restrict__ Wo,
    const float* __restrict__ bo,
    float* __restrict__ out)
{
    __shared__ float As[16][128];
    __shared__ float Bs[16][64];

    int tid = threadIdx.x;
    int m0  = blockIdx.x * 128;
    int n0  = blockIdx.y * 64;
    int tr = tid >> 4, tc = tid & 15;

    u64 acc[8][2];
    #pragma unroll
    for (int j = 0; j < 8; j++){ acc[j][0] = 0ull; acc[j][1] = 0ull; }

    for (int k0 = 0; k0 < C_; k0 += 16){
        int hk = k0 >> 6, dk = k0 & 63;        // K-tile stays within one head (16|64)
        #pragma unroll
        for (int i = 0; i < 2; i++){
            int idx = tid + i * 256;
            int m = idx >> 2, kq = (idx & 3) * 4;
            int mg = m0 + m;
            int b = mg >> 11, t = mg & 2047;
            const float* src = g_att + (((size_t)(b * H_ + hk)) * T_ + t) * D_ + dk + kq;
            float4 v4 = *reinterpret_cast<const float4*>(src);
            As[kq+0][m] = v4.x; As[kq+1][m] = v4.y; As[kq+2][m] = v4.z; As[kq+3][m] = v4.w;
        }
        {
            int r = tid >> 4, cq = (tid & 15) * 4;
            *reinterpret_cast<float4*>(&Bs[r][cq]) =
                *reinterpret_cast<const float4*>(Wo + (size_t)(k0 + r) * C_ + n0 + cq);
        }
        __syncthreads();
        #pragma unroll
        for (int kk = 0; kk < 16; kk++){
            float4 a0 = *reinterpret_cast<const float4*>(&As[kk][tr*8]);
            float4 a1 = *reinterpret_cast<const float4*>(&As[kk][tr*8+4]);
            float4 bq = *reinterpret_cast<const float4*>(&Bs[kk][tc*4]);
            u64 b01 = pk2(bq.x, bq.y), b23 = pk2(bq.z, bq.w);
            float av[8] = {a0.x,a0.y,a0.z,a0.w,a1.x,a1.y,a1.z,a1.w};
            #pragma unroll
            for (int j = 0; j < 8; j++){
                u64 aj = pk2(av[j], av[j]);
                fma2(acc[j][0], aj, b01);
                fma2(acc[j][1], aj, b23);
            }
        }
        __syncthreads();
    }

    float4 bias = *reinterpret_cast<const float4*>(bo + n0 + tc*4);
    #pragma unroll
    for (int j = 0; j < 8; j++){
        float2 lo = upk2(acc[j][0]);
        float2 hi = upk2(acc[j][1]);
        float4 o = make_float4(lo.x + bias.x, lo.y + bias.y, hi.x + bias.z, hi.y + bias.w);
        *reinterpret_cast<float4*>(out + (size_t)(m0 + tr*8 + j) * C_ + n0 + tc*4) = o;
    }
}

// =====================================================================
extern "C" void kernel_launch(void* const* d_in, const int* in_sizes, int n_in,
                              void* d_out, int out_size)
{
    const float* x  = (const float*)d_in[0];
    const float* Wq = (const float*)d_in[1];
    const float* Wk = (const float*)d_in[2];
    const float* Wv = (const float*)d_in[3];
    const float* Wo = (const float*)d_in[4];
    const float* bo = (const float*)d_in[5];
    float* out = (float*)d_out;

    qkv_kernel   <<<dim3(T_/128, BH_, 3), 256>>>(x, Wq, Wk, Wv);
    colsum_kernel<<<dim3(T_/64,  BH_),    256>>>();
    attn_kernel  <<<dim3(T_/64,  BH_),    256>>>();
    oproj_kernel <<<dim3((B_*T_)/128, C_/64), 256>>>(Wo, bo, out);
}

// round 4
// speedup vs baseline: 3.3569x; 3.3567x over previous
#include <cuda_runtime.h>
#include <cstdint>

#define B_   4
#define H_   16
#define T_   2048
#define C_   1024
#define D_   64
#define BH_  64

__device__ float g_q[BH_*T_*D_];
__device__ float g_k[BH_*T_*D_];
__device__ float g_v[BH_*T_*D_];
__device__ float g_att[BH_*T_*D_];
__device__ float g_invZ[BH_*T_];

__device__ __forceinline__ float to_tf32(float f){
    uint32_t r; asm("cvt.rna.tf32.f32 %0, %1;" : "=r"(r) : "f"(f));
    return __uint_as_float(r);
}
__device__ __forceinline__ uint32_t fbits(float f){ return __float_as_uint(f); }

__device__ __forceinline__ void mma8(float4 &c, const uint32_t* a, const uint32_t* b){
    asm volatile("mma.sync.aligned.m16n8k8.row.col.f32.tf32.tf32.f32 "
        "{%0,%1,%2,%3}, {%4,%5,%6,%7}, {%8,%9}, {%0,%1,%2,%3};"
        : "+f"(c.x), "+f"(c.y), "+f"(c.z), "+f"(c.w)
        : "r"(a[0]), "r"(a[1]), "r"(a[2]), "r"(a[3]), "r"(b[0]), "r"(b[1]));
}

// =====================================================================
// K1: QKV projection. out[t,d] = sum_c x[b,t,c] * W_z[h,c,d]
// Block 128(m) x 64(n), K-chunk 32. 8 warps: 4(m) x 2(n), warp tile 32x32.
// =====================================================================
__global__ __launch_bounds__(256) void qkv_kernel(
    const float* __restrict__ x, const float* __restrict__ Wq,
    const float* __restrict__ Wk, const float* __restrict__ Wv)
{
    __shared__ float As[128][36];   // [m][k], pad 4 (frag row varies by g)
    __shared__ float Bs[32][72];    // [k][n], pad 8 (frag row varies by tg)
    int tid=threadIdx.x, lane=tid&31, warp=tid>>5;
    int g=lane>>2, tg=lane&3;
    int wm=warp&3, wn=warp>>2;
    int bh=blockIdx.y, b=bh>>4, h=bh&15;
    int t0=blockIdx.x*128;
    const float* W = (blockIdx.z==0?Wq:(blockIdx.z==1?Wk:Wv)) + (size_t)h*C_*D_;
    float* out = (blockIdx.z==0?g_q:(blockIdx.z==1?g_k:g_v)) + ((size_t)bh*T_+t0)*D_;
    const float* A = x + ((size_t)b*T_+t0)*C_;

    float4 c[2][4];
    #pragma unroll
    for(int i=0;i<2;i++)
        #pragma unroll
        for(int j=0;j<4;j++) c[i][j]=make_float4(0.f,0.f,0.f,0.f);

    for(int k0=0;k0<C_;k0+=32){
        __syncthreads();
        #pragma unroll
        for(int i=0;i<4;i++){
            int idx=tid+i*256, m=idx>>3, kq=(idx&7)*4;
            float4 v=*(const float4*)(A+(size_t)m*C_+k0+kq);
            As[m][kq]=to_tf32(v.x); As[m][kq+1]=to_tf32(v.y);
            As[m][kq+2]=to_tf32(v.z); As[m][kq+3]=to_tf32(v.w);
        }
        #pragma unroll
        for(int i=0;i<2;i++){
            int idx=tid+i*256, r=idx>>4, cq=(idx&15)*4;
            float4 v=*(const float4*)(W+(size_t)(k0+r)*D_+cq);
            Bs[r][cq]=to_tf32(v.x); Bs[r][cq+1]=to_tf32(v.y);
            Bs[r][cq+2]=to_tf32(v.z); Bs[r][cq+3]=to_tf32(v.w);
        }
        __syncthreads();
        #pragma unroll
        for(int ks=0;ks<4;ks++){
            uint32_t a[2][4], bf[4][2];
            #pragma unroll
            for(int mt=0;mt<2;mt++){
                int r=wm*32+mt*16;
                a[mt][0]=fbits(As[r+g][ks*8+tg]);
                a[mt][1]=fbits(As[r+g+8][ks*8+tg]);
                a[mt][2]=fbits(As[r+g][ks*8+tg+4]);
                a[mt][3]=fbits(As[r+g+8][ks*8+tg+4]);
            }
            #pragma unroll
            for(int nt=0;nt<4;nt++){
                int cn=wn*32+nt*8+g;
                bf[nt][0]=fbits(Bs[ks*8+tg][cn]);
                bf[nt][1]=fbits(Bs[ks*8+tg+4][cn]);
            }
            #pragma unroll
            for(int mt=0;mt<2;mt++)
                #pragma unroll
                for(int nt=0;nt<4;nt++) mma8(c[mt][nt], a[mt], bf[nt]);
        }
    }
    #pragma unroll
    for(int mt=0;mt<2;mt++){
        int r=wm*32+mt*16;
        #pragma unroll
        for(int nt=0;nt<4;nt++){
            int cn=wn*32+nt*8+2*tg;
            *(float2*)(out+(size_t)(r+g)*D_+cn)   = make_float2(c[mt][nt].x, c[mt][nt].y);
            *(float2*)(out+(size_t)(r+g+8)*D_+cn) = make_float2(c[mt][nt].z, c[mt][nt].w);
        }
    }
}

// =====================================================================
// K2: per-key Z. S^T = K . Q^T : A=K[s][d] (m=s), B[k=d][n=t]=Q[t][d].
// Block: 64 keys x streamed 64-query tiles. invZ[s] = 1/sum_t exp(.125*S).
// 8 warps: 2(m) x 4(n), warp tile 32(s) x 16(t).
// =====================================================================
__global__ __launch_bounds__(256) void colsum_kernel()
{
    __shared__ float Ks[64][68];
    __shared__ float Qs[64][68];
    __shared__ float zsh[64];
    int tid=threadIdx.x, lane=tid&31, warp=tid>>5;
    int g=lane>>2, tg=lane&3;
    int wm=warp&1, wn=warp>>1;
    int bh=blockIdx.y, s0=blockIdx.x*64;
    const float* kb=g_k+(size_t)bh*T_*D_;
    const float* qb=g_q+(size_t)bh*T_*D_;
    if(tid<64) zsh[tid]=0.f;
    #pragma unroll
    for(int i=0;i<4;i++){
        int idx=tid+i*256, r=idx>>4, cq=(idx&15)*4;
        float4 v=*(const float4*)(kb+(size_t)(s0+r)*D_+cq);
        Ks[r][cq]=to_tf32(v.x); Ks[r][cq+1]=to_tf32(v.y);
        Ks[r][cq+2]=to_tf32(v.z); Ks[r][cq+3]=to_tf32(v.w);
    }
    float z0[2][2]={{0.f,0.f},{0.f,0.f}};   // [mt][row g / g+8]
    for(int t0=s0;t0<T_;t0+=64){
        __syncthreads();
        #pragma unroll
        for(int i=0;i<4;i++){
            int idx=tid+i*256, r=idx>>4, cq=(idx&15)*4;
            float4 v=*(const float4*)(qb+(size_t)(t0+r)*D_+cq);
            Qs[r][cq]=to_tf32(v.x); Qs[r][cq+1]=to_tf32(v.y);
            Qs[r][cq+2]=to_tf32(v.z); Qs[r][cq+3]=to_tf32(v.w);
        }
        __syncthreads();
        float4 c[2][2];
        #pragma unroll
        for(int i=0;i<2;i++){ c[i][0]=make_float4(0.f,0.f,0.f,0.f); c[i][1]=make_float4(0.f,0.f,0.f,0.f); }
        #pragma unroll
        for(int ks=0;ks<8;ks++){
            uint32_t a[2][4], bf[2][2];
            #pragma unroll
            for(int mt=0;mt<2;mt++){
                int r=wm*32+mt*16;
                a[mt][0]=fbits(Ks[r+g][ks*8+tg]);
                a[mt][1]=fbits(Ks[r+g+8][ks*8+tg]);
                a[mt][2]=fbits(Ks[r+g][ks*8+tg+4]);
                a[mt][3]=fbits(Ks[r+g+8][ks*8+tg+4]);
            }
            #pragma unroll
            for(int nt=0;nt<2;nt++){
                int cn=wn*16+nt*8+g;
                bf[nt][0]=fbits(Qs[cn][ks*8+tg]);
                bf[nt][1]=fbits(Qs[cn][ks*8+tg+4]);
            }
            #pragma unroll
            for(int mt=0;mt<2;mt++)
                #pragma unroll
                for(int nt=0;nt<2;nt++) mma8(c[mt][nt], a[mt], bf[nt]);
        }
        bool diag=(t0==s0);
        #pragma unroll
        for(int mt=0;mt<2;mt++){
            int sr0=s0+wm*32+mt*16+g, sr1=sr0+8;
            #pragma unroll
            for(int nt=0;nt<2;nt++){
                int tc0=t0+wn*16+nt*8+2*tg, tc1=tc0+1;
                float4 S=c[mt][nt];
                z0[mt][0] += (!diag||tc0>=sr0)?__expf(S.x*0.125f):0.f;
                z0[mt][0] += (!diag||tc1>=sr0)?__expf(S.y*0.125f):0.f;
                z0[mt][1] += (!diag||tc0>=sr1)?__expf(S.z*0.125f):0.f;
                z0[mt][1] += (!diag||tc1>=sr1)?__expf(S.w*0.125f):0.f;
            }
        }
    }
    #pragma unroll
    for(int mt=0;mt<2;mt++)
        #pragma unroll
        for(int rr=0;rr<2;rr++){
            float v=z0[mt][rr];
            v += __shfl_xor_sync(0xffffffffu, v, 1);
            v += __shfl_xor_sync(0xffffffffu, v, 2);
            if(tg==0) atomicAdd(&zsh[wm*32+mt*16+g+rr*8], v);
        }
    __syncthreads();
    if(tid<64) g_invZ[(size_t)bh*T_+s0+tid]=1.0f/zsh[tid];
}

// =====================================================================
// K3: out[t] = sum_{s<=t} exp(.125*q.k)*invZ[s]*v[s].
// Block: 64 queries, 32-key s-tiles. stage1 S=Q.K^T (N=32), exp->Ps smem,
// stage2 O += P.V (N=64, K=32). 8 warps: 2(m) x 4(n).
// =====================================================================
__global__ __launch_bounds__(256) void attn_kernel()
{
    __shared__ float Qs[64][68];
    __shared__ float Ks[32][68];
    __shared__ float Vs[32][72];
    __shared__ float Ps[64][36];
    __shared__ float izs[32];
    int tid=threadIdx.x, lane=tid&31, warp=tid>>5;
    int g=lane>>2, tg=lane&3;
    int wm=warp&1, wn=warp>>1;
    int bh=blockIdx.y;
    int t0=((int)gridDim.x-1-(int)blockIdx.x)*64;   // big tiles first
    const float* qb=g_q+(size_t)bh*T_*D_;
    const float* kb=g_k+(size_t)bh*T_*D_;
    const float* vb=g_v+(size_t)bh*T_*D_;
    const float* iz=g_invZ+(size_t)bh*T_;

    #pragma unroll
    for(int i=0;i<4;i++){
        int idx=tid+i*256, r=idx>>4, cq=(idx&15)*4;
        float4 v=*(const float4*)(qb+(size_t)(t0+r)*D_+cq);
        Qs[r][cq]=to_tf32(v.x); Qs[r][cq+1]=to_tf32(v.y);
        Qs[r][cq+2]=to_tf32(v.z); Qs[r][cq+3]=to_tf32(v.w);
    }

    float4 oacc[2][2];
    #pragma unroll
    for(int i=0;i<2;i++){ oacc[i][0]=make_float4(0.f,0.f,0.f,0.f); oacc[i][1]=make_float4(0.f,0.f,0.f,0.f); }

    for(int s0=0;s0<=t0+32;s0+=32){
        __syncthreads();
        #pragma unroll
        for(int i=0;i<2;i++){
            int idx=tid+i*256, r=idx>>4, cq=(idx&15)*4;
            float4 v=*(const float4*)(kb+(size_t)(s0+r)*D_+cq);
            Ks[r][cq]=to_tf32(v.x); Ks[r][cq+1]=to_tf32(v.y);
            Ks[r][cq+2]=to_tf32(v.z); Ks[r][cq+3]=to_tf32(v.w);
            float4 w=*(const float4*)(vb+(size_t)(s0+r)*D_+cq);
            Vs[r][cq]=to_tf32(w.x); Vs[r][cq+1]=to_tf32(w.y);
            Vs[r][cq+2]=to_tf32(w.z); Vs[r][cq+3]=to_tf32(w.w);
        }
        if(tid<32) izs[tid]=iz[s0+tid];
        __syncthreads();

        // stage1: S tile [64 x 32], warp n-tile = 8 wide
        float4 c1[2];
        c1[0]=make_float4(0.f,0.f,0.f,0.f); c1[1]=make_float4(0.f,0.f,0.f,0.f);
        #pragma unroll
        for(int ks=0;ks<8;ks++){
            uint32_t a[2][4], bf[2];
            #pragma unroll
            for(int mt=0;mt<2;mt++){
                int r=wm*32+mt*16;
                a[mt][0]=fbits(Qs[r+g][ks*8+tg]);
                a[mt][1]=fbits(Qs[r+g+8][ks*8+tg]);
                a[mt][2]=fbits(Qs[r+g][ks*8+tg+4]);
                a[mt][3]=fbits(Qs[r+g+8][ks*8+tg+4]);
            }
            int cn=wn*8+g;
            bf[0]=fbits(Ks[cn][ks*8+tg]);
            bf[1]=fbits(Ks[cn][ks*8+tg+4]);
            mma8(c1[0], a[0], bf);
            mma8(c1[1], a[1], bf);
        }
        bool nomask=(s0<t0);
        #pragma unroll
        for(int mt=0;mt<2;mt++){
            int rl0=wm*32+mt*16+g;
            int tr0=t0+rl0, tr1=tr0+8;
            int sl0=wn*8+2*tg, sl1=sl0+1;
            int sg0=s0+sl0, sg1=s0+sl1;
            float iz0=izs[sl0], iz1=izs[sl1];
            float4 S=c1[mt];
            float w00=(nomask||tr0>=sg0)?__expf(S.x*0.125f)*iz0:0.f;
            float w01=(nomask||tr0>=sg1)?__expf(S.y*0.125f)*iz1:0.f;
            float w10=(nomask||tr1>=sg0)?__expf(S.z*0.125f)*iz0:0.f;
            float w11=(nomask||tr1>=sg1)?__expf(S.w*0.125f)*iz1:0.f;
            *(float2*)&Ps[rl0][sl0]   = make_float2(to_tf32(w00), to_tf32(w01));
            *(float2*)&Ps[rl0+8][sl0] = make_float2(to_tf32(w10), to_tf32(w11));
        }
        __syncthreads();

        // stage2: O += P.V  (K=32, N=64)
        #pragma unroll
        for(int ks=0;ks<4;ks++){
            uint32_t a[2][4], bf[2][2];
            #pragma unroll
            for(int mt=0;mt<2;mt++){
                int r=wm*32+mt*16;
                a[mt][0]=fbits(Ps[r+g][ks*8+tg]);
                a[mt][1]=fbits(Ps[r+g+8][ks*8+tg]);
                a[mt][2]=fbits(Ps[r+g][ks*8+tg+4]);
                a[mt][3]=fbits(Ps[r+g+8][ks*8+tg+4]);
            }
            #pragma unroll
            for(int nt=0;nt<2;nt++){
                int cn=wn*16+nt*8+g;
                bf[nt][0]=fbits(Vs[ks*8+tg][cn]);
                bf[nt][1]=fbits(Vs[ks*8+tg+4][cn]);
            }
            #pragma unroll
            for(int mt=0;mt<2;mt++)
                #pragma unroll
                for(int nt=0;nt<2;nt++) mma8(oacc[mt][nt], a[mt], bf[nt]);
        }
    }

    float* ob=g_att+((size_t)bh*T_+t0)*D_;
    #pragma unroll
    for(int mt=0;mt<2;mt++){
        int r=wm*32+mt*16;
        #pragma unroll
        for(int nt=0;nt<2;nt++){
            int cn=wn*16+nt*8+2*tg;
            *(float2*)(ob+(size_t)(r+g)*D_+cn)   = make_float2(oacc[mt][nt].x, oacc[mt][nt].y);
            *(float2*)(ob+(size_t)(r+g+8)*D_+cn) = make_float2(oacc[mt][nt].z, oacc[mt][nt].w);
        }
    }
}

// =====================================================================
// K4: output projection + bias. M=B*T, N=C, K=C. A = g_att head-interleaved.
// =====================================================================
__global__ __launch_bounds__(256) void oproj_kernel(
    const float* __restrict__ Wo, const float* __restrict__ bo, float* __restrict__ out)
{
    __shared__ float As[128][36];
    __shared__ float Bs[32][72];
    int tid=threadIdx.x, lane=tid&31, warp=tid>>5;
    int g=lane>>2, tg=lane&3;
    int wm=warp&3, wn=warp>>2;
    int m0=blockIdx.x*128, n0=blockIdx.y*64;

    float4 c[2][4];
    #pragma unroll
    for(int i=0;i<2;i++)
        #pragma unroll
        for(int j=0;j<4;j++) c[i][j]=make_float4(0.f,0.f,0.f,0.f);

    for(int k0=0;k0<C_;k0+=32){
        __syncthreads();
        #pragma unroll
        for(int i=0;i<4;i++){
            int idx=tid+i*256, m=idx>>3, kq=(idx&7)*4;
            int mg=m0+m, b=mg>>11, t=mg&2047;
            int k=k0+kq, hk=k>>6, dk=k&63;
            float4 v=*(const float4*)(g_att+(((size_t)(b*H_+hk))*T_+t)*D_+dk);
            As[m][kq]=to_tf32(v.x); As[m][kq+1]=to_tf32(v.y);
            As[m][kq+2]=to_tf32(v.z); As[m][kq+3]=to_tf32(v.w);
        }
        #pragma unroll
        for(int i=0;i<2;i++){
            int idx=tid+i*256, r=idx>>4, cq=(idx&15)*4;
            float4 v=*(const float4*)(Wo+(size_t)(k0+r)*C_+n0+cq);
            Bs[r][cq]=to_tf32(v.x); Bs[r][cq+1]=to_tf32(v.y);
            Bs[r][cq+2]=to_tf32(v.z); Bs[r][cq+3]=to_tf32(v.w);
        }
        __syncthreads();
        #pragma unroll
        for(int ks=0;ks<4;ks++){
            uint32_t a[2][4], bf[4][2];
            #pragma unroll
            for(int mt=0;mt<2;mt++){
                int r=wm*32+mt*16;
                a[mt][0]=fbits(As[r+g][ks*8+tg]);
                a[mt][1]=fbits(As[r+g+8][ks*8+tg]);
                a[mt][2]=fbits(As[r+g][ks*8+tg+4]);
                a[mt][3]=fbits(As[r+g+8][ks*8+tg+4]);
            }
            #pragma unroll
            for(int nt=0;nt<4;nt++){
                int cn=wn*32+nt*8+g;
                bf[nt][0]=fbits(Bs[ks*8+tg][cn]);
                bf[nt][1]=fbits(Bs[ks*8+tg+4][cn]);
            }
            #pragma unroll
            for(int mt=0;mt<2;mt++)
                #pragma unroll
                for(int nt=0;nt<4;nt++) mma8(c[mt][nt], a[mt], bf[nt]);
        }
    }
    #pragma unroll
    for(int mt=0;mt<2;mt++){
        int r=wm*32+mt*16;
        #pragma unroll
        for(int nt=0;nt<4;nt++){
            int cn=n0+wn*32+nt*8+2*tg;
            float b0v=bo[cn], b1v=bo[cn+1];
            *(float2*)(out+(size_t)(m0+r+g)*C_+cn)   = make_float2(c[mt][nt].x+b0v, c[mt][nt].y+b1v);
            *(float2*)(out+(size_t)(m0+r+g+8)*C_+cn) = make_float2(c[mt][nt].z+b0v, c[mt][nt].w+b1v);
        }
    }
}

// =====================================================================
extern "C" void kernel_launch(void* const* d_in, const int* in_sizes, int n_in,
                              void* d_out, int out_size)
{
    const float* x  = (const float*)d_in[0];
    const float* Wq = (const float*)d_in[1];
    const float* Wk = (const float*)d_in[2];
    const float* Wv = (const float*)d_in[3];
    const float* Wo = (const float*)d_in[4];
    const float* bo = (const float*)d_in[5];
    float* out = (float*)d_out;

    qkv_kernel   <<<dim3(T_/128, BH_, 3), 256>>>(x, Wq, Wk, Wv);
    colsum_kernel<<<dim3(T_/64,  BH_),    256>>>();
    attn_kernel  <<<dim3(T_/64,  BH_),    256>>>();
    oproj_kernel <<<dim3((B_*T_)/128, C_/64), 256>>>(Wo, bo, out);
}